// round 9
// baseline (speedup 1.0000x reference)
#include <cuda_runtime.h>
#include <math.h>

#define BB   32
#define TT   512
#define CC   4233
#define UU   64
#define LABT 129
#define ROWE 68                           // 64 odds + blank@64 + pad (16B rows)
#define PADV (-3.4028234663852886e38f)   // jnp.finfo(float32).min
#define FULL 0xffffffffu
#define PD   4                            // prefetch distance

// compact gathered emissions: [B*T + PD pad rows][ROWE]  (~4.5 MB)
__device__ __align__(16) float g_emit[((size_t)BB * TT + PD) * ROWE];
// scratch: Viterbi path indices per (b,t)
__device__ unsigned short g_wi[BB * TT];

// ---------------------------------------------------------------------------
// Phase 1: gather. Row: [0..63]=emit(label_u), [64]=emit(blank).
// ---------------------------------------------------------------------------
__global__ void gather_kernel(const float* __restrict__ logit,
                              const int*   __restrict__ label,
                              const int*   __restrict__ blankp)
{
    const int blank = blankp ? *blankp : 0;
    unsigned idx = blockIdx.x * blockDim.x + threadIdx.x;
    const unsigned total = (unsigned)BB * TT * 65;
    if (idx >= total) return;

    unsigned j  = idx % 65;            // 0..63 label slots, 64 = blank
    unsigned bt = idx / 65;            // b*T + t  (b = bt>>9)

    int c;
    if (j < 64) {
        int l = label[j * BB + (bt >> 9)];
        if (l == blank) l = -1;        // pad sentinel, wraps like jnp % C
        c = l % CC; if (c < 0) c += CC;
    } else {
        c = blank % CC; if (c < 0) c += CC;
    }
    g_emit[(size_t)bt * ROWE + j] = logit[(size_t)bt * CC + (unsigned)c];
}

// ---------------------------------------------------------------------------
// R7-exact LSE steps (natural domain, __expf/__logf) — passing arithmetic
__device__ __forceinline__ float step2f(float e, float a0, float a1, unsigned &d)
{
    float m  = fmaxf(a0, a1);
    float mn = fminf(a0, a1);
    float s  = 1.0f + __expf(mn - m);
    d = (a1 > a0) ? 1u : 0u;
    return e + m + __logf(s);
}

__device__ __forceinline__ float step3f(float e, float a0, float a1, float a2,
                                        bool cond, unsigned &d)
{
    float a2e = cond ? PADV : a2;
    float hi  = fmaxf(a0, a1);
    float lo  = fminf(a0, a1);
    float m   = fmaxf(hi, a2e);
    float sec = fminf(hi, fmaxf(lo, a2e));
    float thr = fminf(lo, a2e);
    float s   = 1.0f + __expf(sec - m) + __expf(thr - m);
    d = (a2e > hi) ? 2u : ((a1 > a0) ? 1u : 0u);
    return e + m + __logf(s);
}

// ---------------------------------------------------------------------------
// Phase 2: TWO batches per warp (half-warp each) to fill dependency bubbles.
// Group g = lane>>4, gl = lane&15. Lane owns j = 8*gl+1 .. 8*gl+8.
// j=0 is the exact blank running-sum z (per group).
// ---------------------------------------------------------------------------
__global__ __launch_bounds__(32, 1)
void dp_kernel(const int* __restrict__ label,
               const int* __restrict__ blankp,
               unsigned short* __restrict__ wi_out,
               float* __restrict__ out_loss)
{
    __shared__ unsigned       dsm32[(TT / 2) * 32];   // 16 delta bits/lane/step
    __shared__ unsigned short wi_sm[2][TT];

    const int lane  = threadIdx.x;
    const int g     = lane >> 4;          // batch group 0/1
    const int gl    = lane & 15;          // lane within group
    const int b     = 2 * blockIdx.x + g;
    const int blank = blankp ? *blankp : 0;
    const unsigned gmask = 0xFFFFu << (g * 16);

    // 4 labels per lane: u = 4*gl .. 4*gl+3
    int labv[4], ejv[4];
    #pragma unroll
    for (int k = 0; k < 4; k++) {
        labv[k] = label[(4 * gl + k) * BB + b];
        ejv[k]  = (labv[k] == blank) ? -1 : labv[k];
    }
    int pej = __shfl_up_sync(FULL, ejv[3], 1);   // neighbor's last label
    if (gl == 0) pej = -1;
    bool cond[4];
    cond[0] = (ejv[0] == blank) || (ejv[0] == pej);
    #pragma unroll
    for (int k = 1; k < 4; k++)
        cond[k] = (ejv[k] == blank) || (ejv[k] == ejv[k - 1]);

    // yl = 2*count(nonblank)+1 per group
    int cnt = 0;
    #pragma unroll
    for (int k = 0; k < 4; k++) {
        unsigned q = __ballot_sync(FULL, labv[k] != blank);
        cnt += __popc(q & gmask);
    }
    const int yl = 2 * cnt + 1;

    const float* __restrict__ rowb = g_emit + (size_t)b * TT * ROWE;
    const float4* pf4 = (const float4*)rowb + gl;       // odds 4gl..4gl+3
    const float*  pfb = rowb + 64;
    const int q4 = ROWE / 4;                            // float4 per row (17)

    float4 eB[PD];
    float  ebB[PD];
    #pragma unroll
    for (int tp = 0; tp < PD; tp++) {
        eB[tp]  = pf4[0];  pf4 += q4;
        ebB[tp] = pfb[0];  pfb += ROWE;
    }

    // ---- t = 0 init ----
    float z  = ebB[0];                                  // dp[0](0)
    float w1 = (gl == 0) ? eB[0].x : PADV;              // dp[1](0)
    float w2 = PADV, w3 = PADV, w4 = PADV;
    float w5 = PADV, w6 = PADV, w7 = PADV, w8 = PADV;
    float pv7 = PADV;                                   // dp_prev[8gl-1]
    float pv8 = (gl == 0) ? z : PADV;                   // dp_prev[8gl]
    eB[0]  = pf4[0];  pf4 += q4;                        // refill with row PD
    ebB[0] = pfb[0];  pfb += ROWE;

    unsigned dacc = 0;

    #pragma unroll 4
    for (int t = 1; t < TT; t++) {
        const int s = t & 3;
        const float4 eo = eB[s];
        const float  eb = ebB[s];
        eB[s]  = pf4[0];  pf4 += q4;                    // row t+PD (padded)
        ebB[s] = pfb[0];  pfb += ROWE;

        unsigned d1, d2, d3, d4, d5, d6, d7, d8;
        const float n1 = step3f(eo.x, w1, pv8, pv7, cond[0], d1); // j=8gl+1
        const float n2 = step2f(eb,  w2, w1, d2);                 // j=8gl+2
        const float n3 = step3f(eo.y, w3, w2, w1, cond[1], d3);   // j=8gl+3
        const float n4 = step2f(eb,  w4, w3, d4);                 // j=8gl+4
        const float n5 = step3f(eo.z, w5, w4, w3, cond[2], d5);   // j=8gl+5
        const float n6 = step2f(eb,  w6, w5, d6);                 // j=8gl+6
        const float n7 = step3f(eo.w, w7, w6, w5, cond[3], d7);   // j=8gl+7
        const float n8 = step2f(eb,  w8, w7, d8);                 // j=8gl+8
        z += eb;                                                  // j=0 exact
        w1 = n1; w2 = n2; w3 = n3; w4 = n4;
        w5 = n5; w6 = n6; w7 = n7; w8 = n8;

        const float s7 = __shfl_up_sync(FULL, w7, 1);
        const float s8 = __shfl_up_sync(FULL, w8, 1);
        pv7 = (gl == 0) ? PADV : s7;
        pv8 = (gl == 0) ? z    : s8;

        const unsigned fld = d1 | (d2 << 2) | (d3 << 4) | (d4 << 6)
                           | (d5 << 8) | (d6 << 10) | (d7 << 12) | (d8 << 14);
        dacc |= fld << ((t & 1) * 16);
        if (t & 1) { dsm32[(t >> 1) * 32 + lane] = dacc; dacc = 0; }
    }
    __syncwarp();

    // ---- terminal values ----
    auto fetch = [&](int idx) -> float {
        idx = ((idx % LABT) + LABT) % LABT;     // jnp negative-wrap safety
        const int src  = g * 16 + ((idx - 1) >> 3);
        const int slot = (idx - 1) & 7;
        const float c0 = __shfl_sync(FULL, w1, src);
        const float c1 = __shfl_sync(FULL, w2, src);
        const float c2 = __shfl_sync(FULL, w3, src);
        const float c3 = __shfl_sync(FULL, w4, src);
        const float c4 = __shfl_sync(FULL, w5, src);
        const float c5 = __shfl_sync(FULL, w6, src);
        const float c6 = __shfl_sync(FULL, w7, src);
        const float c7 = __shfl_sync(FULL, w8, src);
        float r = (slot == 0) ? c0 : (slot == 1) ? c1 : (slot == 2) ? c2 :
                  (slot == 3) ? c3 : (slot == 4) ? c4 : (slot == 5) ? c5 :
                  (slot == 6) ? c6 : c7;
        if (idx == 0) r = z;
        return r;
    };
    const float dv1 = fetch(yl - 1);
    const float dv2 = fetch(yl - 2);

    // ---- dual-group speculative backtrack (wi non-increasing) ----
    {
        int wi = (dv1 > dv2) ? (yl - 1) : (yl - 2);
        int t  = TT - 1;                        // uniform within group
        while (__any_sync(FULL, t >= 1)) {
            const int tt = t - gl;
            const bool valid = (t >= 1) && (tt >= 1);
            int d = 0;
            if (valid && wi > 0) {
                const unsigned word =
                    dsm32[(tt >> 1) * 32 + g * 16 + ((wi - 1) >> 3)];
                d = (int)((word >> (((tt & 1) * 16) + ((wi - 1) & 7) * 2)) & 3u);
            }
            const unsigned nzf = __ballot_sync(FULL, valid && (d != 0));
            const unsigned nz  = (nzf >> (g * 16)) & 0xFFFFu;
            const int nvalid = (t < 1) ? 0 : ((t < 16) ? t : 16);
            const int first  = nz ? (__ffs(nz) - 1) : 16;
            const int adv    = (first + 1 < nvalid) ? (first + 1) : nvalid;
            if (gl < adv) wi_sm[g][tt] = (unsigned short)wi;
            const int srcl = g * 16 + ((first < 15) ? first : 15);
            const int dfirst = __shfl_sync(FULL, d, srcl);
            if (first < nvalid) wi -= dfirst;
            t -= adv;
        }
        if (gl == 0) {
            wi_sm[g][0] = (unsigned short)wi;
            const float mm  = fmaxf(dv1, dv2);
            const float lse = mm + log1pf(expf(-fabsf(dv1 - dv2)));
            if (out_loss) out_loss[b] = -2.0f * lse / (float)(yl - 1);
        }
    }
    __syncwarp();

    for (int t = gl; t < TT; t += 16)
        wi_out[b * TT + t] = wi_sm[g][t];
}

// ---------------------------------------------------------------------------
// One warp per (b,t) row: broadcast wi, contiguous one-hot stores
// ---------------------------------------------------------------------------
__global__ void align_kernel(const unsigned short* __restrict__ wi,
                             float* __restrict__ out)
{
    const int w    = (blockIdx.x * blockDim.x + threadIdx.x) >> 5;  // row = b*T+t
    const int lane = threadIdx.x & 31;
    if (w >= BB * TT) return;
    const int wiv = (int)wi[w];
    float* row = out + (size_t)w * LABT;
    #pragma unroll
    for (int j = lane; j < LABT; j += 32)
        row[j] = (j == wiv) ? 1.0f : 0.0f;
}

// ---------------------------------------------------------------------------
extern "C" void kernel_launch(void* const* d_in, const int* in_sizes, int n_in,
                              void* d_out, int out_size)
{
    const float* logit  = (const float*)d_in[0];
    const int*   label  = (const int*)d_in[1];
    const int*   blankp = (n_in >= 3) ? (const int*)d_in[2] : nullptr;

    float* out = (float*)d_out;
    const size_t align_elems = (size_t)BB * TT * LABT;   // 2,113,536
    float* out_loss = ((size_t)out_size >= align_elems + BB) ? (out + align_elems)
                                                             : nullptr;

    unsigned short* wi;
    cudaGetSymbolAddress((void**)&wi, g_wi);

    const int gtotal = BB * TT * 65;
    gather_kernel<<<(gtotal + 255) / 256, 256>>>(logit, label, blankp);
    dp_kernel<<<BB / 2, 32>>>(label, blankp, wi, out_loss);
    align_kernel<<<(BB * TT * 32 + 255) / 256, 256>>>(wi, out);
}

// round 14
// speedup vs baseline: 2.1181x; 2.1181x over previous
#include <cuda_runtime.h>
#include <math.h>

#define BB   32
#define TT   512
#define CC   4233
#define UU   64
#define LABT 129
#define ROWE 68                           // 64 odds + blank@64 + pad (16B rows)
#define PADV (-3.4028234663852886e38f)   // jnp.finfo(float32).min
#define FULL 0xffffffffu
#define PD   4                            // prefetch distance

// compact gathered emissions: [B*T + PD pad rows][ROWE]
__device__ __align__(16) float g_emit[((size_t)BB * TT + PD) * ROWE];
// scratch: Viterbi path indices per (b,t)
__device__ unsigned short g_wi[BB * TT];

// ---------------------------------------------------------------------------
// Phase 1: gather. Row: [0..63]=emit(label_u), [64]=emit(blank).
// ---------------------------------------------------------------------------
__global__ void gather_kernel(const float* __restrict__ logit,
                              const int*   __restrict__ label,
                              const int*   __restrict__ blankp)
{
    const int blank = blankp ? *blankp : 0;
    unsigned idx = blockIdx.x * blockDim.x + threadIdx.x;
    const unsigned total = (unsigned)BB * TT * 65;
    if (idx >= total) return;

    unsigned j  = idx % 65;            // 0..63 label slots, 64 = blank
    unsigned bt = idx / 65;            // b*T + t  (b = bt>>9)

    int c;
    if (j < 64) {
        int l = label[j * BB + (bt >> 9)];
        if (l == blank) l = -1;        // pad sentinel, wraps like jnp % C
        c = l % CC; if (c < 0) c += CC;
    } else {
        c = blank % CC; if (c < 0) c += CC;
    }
    g_emit[(size_t)bt * ROWE + j] = logit[(size_t)bt * CC + (unsigned)c];
}

// ---------------------------------------------------------------------------
// Phase 2: 128 threads per batch, ONE position per lane (j = gl+1).
// j=0 is lane 0's exact blank running-sum z. One __syncthreads per step.
// Uniform 3-term LSE: even positions have cond=true, which reduces it exactly
// to the 2-term form (a2 term underflows to +0.0f) — R7-identical arithmetic.
// ---------------------------------------------------------------------------
__global__ __launch_bounds__(128, 1)
void dp_kernel(const int* __restrict__ label,
               const int* __restrict__ blankp,
               unsigned short* __restrict__ wi_out,
               float* __restrict__ out_loss)
{
    __shared__ float          buf[2][132];     // [0]=PADV pad, [j+1]=dp[j]
    __shared__ unsigned char  dsm[TT / 4][128];// 4 steps x 2bit per (grp, lane)
    __shared__ unsigned short wi_sm[TT];

    const int gl    = threadIdx.x;             // 0..127, owns j = gl+1
    const int b     = blockIdx.x;
    const int blank = blankp ? *blankp : 0;

    // cond for my position (odd j = even gl uses labels; even j: true)
    const int myu  = gl >> 1;
    const int lab  = label[myu * BB + b];
    const int labp = (myu > 0) ? label[(myu - 1) * BB + b] : blank;
    const int ej   = (lab  == blank) ? -1 : lab;
    const int ejp  = (myu > 0) ? ((labp == blank) ? -1 : labp) : -1;
    const bool cond = (gl & 1) ? true
                               : ((ej == blank) || (ej == ejp));

    // emission pointer: even gl -> label slot gl/2, odd gl -> blank slot 64
    const float* __restrict__ base = g_emit + (size_t)b * TT * ROWE;
    const float* pe = base + ((gl & 1) ? 64 : (gl >> 1));
    const float* pb = base + 64;               // blank stream (lane 0's z)

    float eB[PD], ebB[PD];
    #pragma unroll
    for (int tp = 0; tp < PD; tp++) {
        eB[tp] = pe[0];  pe += ROWE;
        if (gl == 0) { ebB[tp] = pb[0]; }  pb += ROWE;
    }

    // ---- t = 0 init ----
    float z   = (gl == 0) ? ebB[0] : 0.0f;     // dp[0](0) (lane 0 only)
    float myv = (gl == 0) ? eB[0] : PADV;      // dp[1](0) on lane 0, else PADV
    // PIPELINE FIX: slot 0 was consumed at t=0 — refill it with row PD
    eB[0] = pe[0];  pe += ROWE;
    if (gl == 0) { ebB[0] = pb[0]; }  pb += ROWE;

    buf[0][0] = PADV; buf[1][0] = PADV;        // pad slots (j=-1)
    buf[0][gl + 2] = myv;
    if (gl == 0) buf[0][1] = z;
    unsigned dacc = 0;
    __syncthreads();

    // ---- main recurrence ----
    #pragma unroll 4
    for (int t = 1; t < TT; t++) {
        const int c = t & 1, p = c ^ 1, s = t & 3;
        const float e = eB[s];
        eB[s] = pe[0];  pe += ROWE;            // prefetch t+PD (padded, safe)
        float ebv = 0.0f;
        if (gl == 0) { ebv = ebB[s]; ebB[s] = pb[0]; }
        pb += ROWE;

        const float a1 = buf[p][gl + 1];       // dp_prev[j-1]
        const float a2 = buf[p][gl];           // dp_prev[j-2] (PADV at j=1)

        // uniform 3-term LSE (R7-exact ops)
        const float a2e = cond ? PADV : a2;
        const float hi  = fmaxf(myv, a1);
        const float lo  = fminf(myv, a1);
        const float m   = fmaxf(hi, a2e);
        const float sec = fminf(hi, fmaxf(lo, a2e));
        const float thr = fminf(lo, a2e);
        const float sum = 1.0f + __expf(sec - m) + __expf(thr - m);
        const unsigned d = (a2e > hi) ? 2u : ((a1 > myv) ? 1u : 0u);
        myv = e + m + __logf(sum);

        buf[c][gl + 2] = myv;
        if (gl == 0) { z += ebv; buf[c][1] = z; }

        dacc |= d << (2 * s);
        if (s == 3) { dsm[t >> 2][gl] = (unsigned char)dacc; dacc = 0; }
        __syncthreads();
    }

    // ---- yl (count over even lanes' labels) ----
    const int cnt = __syncthreads_count(((gl & 1) == 0) && (lab != blank));
    const int yl  = 2 * cnt + 1;

    const float* last = buf[(TT - 1) & 1];
    auto widx = [&](int idx) { return ((idx % LABT) + LABT) % LABT; };
    const float dv1 = last[widx(yl - 1) + 1];
    const float dv2 = last[widx(yl - 2) + 1];

    // ---- warp-0 speculative backtrack (wi non-increasing) ----
    if (gl < 32) {
        int wi = (dv1 > dv2) ? (yl - 1) : (yl - 2);
        int t  = TT - 1;
        while (t >= 1) {
            const int tt = t - gl;
            const bool valid = (tt >= 1);
            int d = 0;
            if (valid && wi > 0)
                d = (int)((dsm[tt >> 2][wi - 1] >> (2 * (tt & 3))) & 3u);
            const unsigned nz = __ballot_sync(FULL, valid && (d != 0));
            const int nvalid = (t < 32) ? t : 32;
            const int first  = nz ? (__ffs(nz) - 1) : 32;
            const int adv    = (first + 1 < nvalid) ? (first + 1) : nvalid;
            if (gl < adv) wi_sm[tt] = (unsigned short)wi;
            const int dfirst = __shfl_sync(FULL, d, (first < 31) ? first : 31);
            if (first < nvalid) wi -= dfirst;
            t -= adv;
        }
        if (gl == 0) {
            wi_sm[0] = (unsigned short)wi;
            const float mm  = fmaxf(dv1, dv2);
            const float lse = mm + log1pf(expf(-fabsf(dv1 - dv2)));
            if (out_loss) out_loss[b] = -2.0f * lse / (float)(yl - 1);
        }
    }
    __syncthreads();

    for (int t = gl; t < TT; t += 128)
        wi_out[b * TT + t] = wi_sm[t];
}

// ---------------------------------------------------------------------------
// One warp per (b,t) row: broadcast wi, contiguous one-hot stores
// ---------------------------------------------------------------------------
__global__ void align_kernel(const unsigned short* __restrict__ wi,
                             float* __restrict__ out)
{
    const int w    = (blockIdx.x * blockDim.x + threadIdx.x) >> 5;  // row = b*T+t
    const int lane = threadIdx.x & 31;
    if (w >= BB * TT) return;
    const int wiv = (int)wi[w];
    float* row = out + (size_t)w * LABT;
    #pragma unroll
    for (int j = lane; j < LABT; j += 32)
        row[j] = (j == wiv) ? 1.0f : 0.0f;
}

// ---------------------------------------------------------------------------
extern "C" void kernel_launch(void* const* d_in, const int* in_sizes, int n_in,
                              void* d_out, int out_size)
{
    const float* logit  = (const float*)d_in[0];
    const int*   label  = (const int*)d_in[1];
    const int*   blankp = (n_in >= 3) ? (const int*)d_in[2] : nullptr;

    float* out = (float*)d_out;
    const size_t align_elems = (size_t)BB * TT * LABT;   // 2,113,536
    float* out_loss = ((size_t)out_size >= align_elems + BB) ? (out + align_elems)
                                                             : nullptr;

    unsigned short* wi;
    cudaGetSymbolAddress((void**)&wi, g_wi);

    const int gtotal = BB * TT * 65;
    gather_kernel<<<(gtotal + 255) / 256, 256>>>(logit, label, blankp);
    dp_kernel<<<BB, 128>>>(label, blankp, wi, out_loss);
    align_kernel<<<(BB * TT * 32 + 255) / 256, 256>>>(wi, out);
}